// round 5
// baseline (speedup 1.0000x reference)
#include <cuda_runtime.h>
#include <cuda_bf16.h>
#include <cstdint>
#include <cstddef>

// Problem constants
#define Bc   4
#define Sc   1024
#define Dc   1024
#define Hc   16
#define HDc  64
#define Mrows (Bc * Sc)          // 4096
#define NQKV  (3 * Dc)           // 3072

static const long OUT_ELEMS = (long)Bc * Sc * Dc;        // 4,194,304
static const long ATT_ELEMS = (long)Bc * Hc * Sc * Sc;   // 67,108,864

// Scratch (device globals — no allocations allowed)
__device__ float g_qkv[(size_t)Mrows * NQKV];            // 50 MB
__device__ float g_ctx[(size_t)Mrows * Dc];              // 16 MB
__device__ float g_att[(size_t)Bc * Hc * Sc * Sc];       // 268 MB (fallback if att not an output)

// ---------------------------------------------------------------------------
// Generic SGEMM with bias:  C[M,N] = A[M,K] @ B[K,N] + bias[N]
// 128x128 block tile, BK=8, 256 threads, 8x8 per-thread microtile.
// All dims divisible by tile sizes for this problem (no bounds checks).
// ---------------------------------------------------------------------------
__global__ __launch_bounds__(256) void sgemm_bias_kernel(
    const float* __restrict__ A, const float* __restrict__ B,
    const float* __restrict__ bias, float* __restrict__ C,
    int Md, int Nd, int Kd)
{
    __shared__ float As[8][128];
    __shared__ float Bs[8][128];

    const int t  = threadIdx.x;
    const int m0 = blockIdx.y * 128;
    const int n0 = blockIdx.x * 128;
    const int tx = t & 15;          // 16 col-groups of 8
    const int ty = t >> 4;          // 16 row-groups of 8

    const int arow = t >> 1;        // 0..127
    const int ac4  = (t & 1) * 4;   // 0 or 4
    const int brow = t >> 5;        // 0..7
    const int bc4  = (t & 31) * 4;  // 0..124

    float acc[8][8];
#pragma unroll
    for (int i = 0; i < 8; ++i)
#pragma unroll
        for (int j = 0; j < 8; ++j) acc[i][j] = 0.0f;

    for (int k0 = 0; k0 < Kd; k0 += 8) {
        float4 av = *(const float4*)&A[(size_t)(m0 + arow) * Kd + k0 + ac4];
        float4 bv = *(const float4*)&B[(size_t)(k0 + brow) * Nd + n0 + bc4];
        As[ac4 + 0][arow] = av.x;
        As[ac4 + 1][arow] = av.y;
        As[ac4 + 2][arow] = av.z;
        As[ac4 + 3][arow] = av.w;
        *(float4*)&Bs[brow][bc4] = bv;
        __syncthreads();

#pragma unroll
        for (int k = 0; k < 8; ++k) {
            float ra[8], rb[8];
#pragma unroll
            for (int i = 0; i < 8; ++i) ra[i] = As[k][ty * 8 + i];
#pragma unroll
            for (int j = 0; j < 8; ++j) rb[j] = Bs[k][tx * 8 + j];
#pragma unroll
            for (int i = 0; i < 8; ++i)
#pragma unroll
                for (int j = 0; j < 8; ++j)
                    acc[i][j] = fmaf(ra[i], rb[j], acc[i][j]);
        }
        __syncthreads();
    }

#pragma unroll
    for (int i = 0; i < 8; ++i) {
        const int gm = m0 + ty * 8 + i;
#pragma unroll
        for (int j = 0; j < 8; j += 4) {
            const int gn = n0 + tx * 8 + j;
            float4 v;
            v.x = acc[i][j + 0] + bias[gn + 0];
            v.y = acc[i][j + 1] + bias[gn + 1];
            v.z = acc[i][j + 2] + bias[gn + 2];
            v.w = acc[i][j + 3] + bias[gn + 3];
            *(float4*)&C[(size_t)gm * Nd + gn] = v;
        }
    }
}

// ---------------------------------------------------------------------------
// scores[b,h,m,n] = (Q[b,h,m,:] . K[b,h,n,:]) * scale + mask[b,m,n]
// Q/K strided inside g_qkv: row (b*S+s)*3072, head offset h*192 (+64 for K).
// 128x128 tile per block, K-dim = 64 processed in chunks of 16.
// ---------------------------------------------------------------------------
__global__ __launch_bounds__(256) void scores_kernel(
    const float* __restrict__ qkv, const float* __restrict__ mask,
    float* __restrict__ att)
{
    __shared__ float Qs[16][128];
    __shared__ float Ks[16][128];

    const int t  = threadIdx.x;
    const int bh = blockIdx.z;
    const int b  = bh >> 4;
    const int h  = bh & 15;
    const int m0 = blockIdx.y * 128;
    const int n0 = blockIdx.x * 128;
    const int tx = t & 15;
    const int ty = t >> 4;

    const size_t qbase = (size_t)b * Sc * NQKV + (size_t)h * 192;

    float acc[8][8];
#pragma unroll
    for (int i = 0; i < 8; ++i)
#pragma unroll
        for (int j = 0; j < 8; ++j) acc[i][j] = 0.0f;

    for (int k0 = 0; k0 < 64; k0 += 16) {
#pragma unroll
        for (int r = 0; r < 2; ++r) {
            const int idx = t * 2 + r;       // 0..511
            const int row = idx >> 2;        // 0..127
            const int c4  = (idx & 3) * 4;   // 0..12
            float4 qv = *(const float4*)&qkv[qbase + (size_t)(m0 + row) * NQKV + k0 + c4];
            float4 kv = *(const float4*)&qkv[qbase + (size_t)(n0 + row) * NQKV + 64 + k0 + c4];
            Qs[c4 + 0][row] = qv.x; Qs[c4 + 1][row] = qv.y;
            Qs[c4 + 2][row] = qv.z; Qs[c4 + 3][row] = qv.w;
            Ks[c4 + 0][row] = kv.x; Ks[c4 + 1][row] = kv.y;
            Ks[c4 + 2][row] = kv.z; Ks[c4 + 3][row] = kv.w;
        }
        __syncthreads();

#pragma unroll
        for (int k = 0; k < 16; ++k) {
            float ra[8], rb[8];
#pragma unroll
            for (int i = 0; i < 8; ++i) ra[i] = Qs[k][ty * 8 + i];
#pragma unroll
            for (int j = 0; j < 8; ++j) rb[j] = Ks[k][tx * 8 + j];
#pragma unroll
            for (int i = 0; i < 8; ++i)
#pragma unroll
                for (int j = 0; j < 8; ++j)
                    acc[i][j] = fmaf(ra[i], rb[j], acc[i][j]);
        }
        __syncthreads();
    }

    const float scale = 0.125f;  // 1/sqrt(64)
    const float* mbase = mask + (size_t)b * Sc * Sc;
    float* abase = att + (size_t)bh * Sc * Sc;

#pragma unroll
    for (int i = 0; i < 8; ++i) {
        const int gm = m0 + ty * 8 + i;
#pragma unroll
        for (int j = 0; j < 8; j += 4) {
            const int gn = n0 + tx * 8 + j;
            float4 mv = *(const float4*)&mbase[(size_t)gm * Sc + gn];
            float4 v;
            v.x = fmaf(acc[i][j + 0], scale, mv.x);
            v.y = fmaf(acc[i][j + 1], scale, mv.y);
            v.z = fmaf(acc[i][j + 2], scale, mv.z);
            v.w = fmaf(acc[i][j + 3], scale, mv.w);
            *(float4*)&abase[(size_t)gm * Sc + gn] = v;
        }
    }
}

// ---------------------------------------------------------------------------
// In-place row softmax. One block of 256 threads per row of 1024 floats.
// ---------------------------------------------------------------------------
__global__ __launch_bounds__(256) void softmax_kernel(float* __restrict__ att)
{
    __shared__ float red[256];
    float* row = att + (size_t)blockIdx.x * Sc;
    const int t = threadIdx.x;

    float4 v = *(float4*)&row[t * 4];
    float mx = fmaxf(fmaxf(v.x, v.y), fmaxf(v.z, v.w));
    red[t] = mx;
    __syncthreads();
#pragma unroll
    for (int s = 128; s > 0; s >>= 1) {
        if (t < s) red[t] = fmaxf(red[t], red[t + s]);
        __syncthreads();
    }
    mx = red[0];
    __syncthreads();

    v.x = __expf(v.x - mx);
    v.y = __expf(v.y - mx);
    v.z = __expf(v.z - mx);
    v.w = __expf(v.w - mx);

    red[t] = v.x + v.y + v.z + v.w;
    __syncthreads();
#pragma unroll
    for (int s = 128; s > 0; s >>= 1) {
        if (t < s) red[t] += red[t + s];
        __syncthreads();
    }
    const float inv = 1.0f / red[0];

    v.x *= inv; v.y *= inv; v.z *= inv; v.w *= inv;
    *(float4*)&row[t * 4] = v;
}

// ---------------------------------------------------------------------------
// ctx[b, m, h, :] = att[b,h,m,:] @ V[b,h,:,:]     (per (b,h): [1024,1024]@[1024,64])
// 128x64 block tile, BK=16, 256 threads, 8x4 per-thread microtile.
// ctx stored [b, s, h, hd] row-major -> plain [4096,1024] for the out-proj GEMM.
// ---------------------------------------------------------------------------
__global__ __launch_bounds__(256) void ctx_kernel(
    const float* __restrict__ att, const float* __restrict__ qkv,
    float* __restrict__ ctx)
{
    __shared__ float As[16][128];  // att tile, transposed [k][m]
    __shared__ float Vs[16][64];

    const int t  = threadIdx.x;
    const int bh = blockIdx.z;
    const int b  = bh >> 4;
    const int h  = bh & 15;
    const int m0 = blockIdx.y * 128;
    const int tx = t & 15;   // 16 col-groups of 4 -> 64 cols
    const int ty = t >> 4;   // 16 row-groups of 8 -> 128 rows

    const float* abase = att + (size_t)bh * Sc * Sc;
    const size_t vbase = (size_t)b * Sc * NQKV + (size_t)h * 192 + 128;

    float acc[8][4];
#pragma unroll
    for (int i = 0; i < 8; ++i)
#pragma unroll
        for (int j = 0; j < 4; ++j) acc[i][j] = 0.0f;

    for (int k0 = 0; k0 < Sc; k0 += 16) {
#pragma unroll
        for (int r = 0; r < 2; ++r) {
            const int idx = t * 2 + r;
            const int row = idx >> 2;
            const int c4  = (idx & 3) * 4;
            float4 av = *(const float4*)&abase[(size_t)(m0 + row) * Sc + k0 + c4];
            As[c4 + 0][row] = av.x; As[c4 + 1][row] = av.y;
            As[c4 + 2][row] = av.z; As[c4 + 3][row] = av.w;
        }
        {
            const int r  = t >> 4;         // 0..15
            const int c4 = (t & 15) * 4;   // 0..60
            float4 vv = *(const float4*)&qkv[vbase + (size_t)(k0 + r) * NQKV + c4];
            *(float4*)&Vs[r][c4] = vv;
        }
        __syncthreads();

#pragma unroll
        for (int k = 0; k < 16; ++k) {
            float ra[8], rb[4];
#pragma unroll
            for (int i = 0; i < 8; ++i) ra[i] = As[k][ty * 8 + i];
#pragma unroll
            for (int j = 0; j < 4; ++j) rb[j] = Vs[k][tx * 4 + j];
#pragma unroll
            for (int i = 0; i < 8; ++i)
#pragma unroll
                for (int j = 0; j < 4; ++j)
                    acc[i][j] = fmaf(ra[i], rb[j], acc[i][j]);
        }
        __syncthreads();
    }

#pragma unroll
    for (int i = 0; i < 8; ++i) {
        const int gm = m0 + ty * 8 + i;                 // seq position
        float4 v;
        v.x = acc[i][0]; v.y = acc[i][1]; v.z = acc[i][2]; v.w = acc[i][3];
        *(float4*)&ctx[(size_t)(b * Sc + gm) * Dc + h * HDc + tx * 4] = v;
    }
}

// ---------------------------------------------------------------------------
// Launch
// ---------------------------------------------------------------------------
extern "C" void kernel_launch(void* const* d_in, const int* in_sizes, int n_in,
                              void* d_out, int out_size)
{
    const float* x    = (const float*)d_in[0];
    const float* mask = (const float*)d_in[1];
    const float* Wqkv = (const float*)d_in[2];
    const float* bqkv = (const float*)d_in[3];
    const float* Wo   = (const float*)d_in[4];
    const float* bo   = (const float*)d_in[5];

    float *qkvp, *ctxp, *attScr;
    cudaGetSymbolAddress((void**)&qkvp,  g_qkv);
    cudaGetSymbolAddress((void**)&ctxp,  g_ctx);
    cudaGetSymbolAddress((void**)&attScr, g_att);

    float* outp = (float*)d_out;
    float* attp;
    if ((long)out_size >= OUT_ELEMS + ATT_ELEMS) {
        attp = (float*)d_out + OUT_ELEMS;          // tuple flattened: out, then att
    } else if ((long)out_size == ATT_ELEMS) {
        attp = (float*)d_out;                      // att-only output
        outp = qkvp;                               // sink (qkv dead by then)
    } else {
        attp = attScr;                             // out-only output
    }

    // 1. qkv = x @ Wqkv + bqkv        [4096,3072]
    {
        dim3 grid(NQKV / 128, Mrows / 128);
        sgemm_bias_kernel<<<grid, 256>>>(x, Wqkv, bqkv, qkvp, Mrows, NQKV, Dc);
    }
    // 2. scores (+mask, *scale) -> att buffer
    {
        dim3 grid(Sc / 128, Sc / 128, Bc * Hc);
        scores_kernel<<<grid, 256>>>(qkvp, mask, attp);
    }
    // 3. softmax rows in place
    softmax_kernel<<<Bc * Hc * Sc, 256>>>(attp);
    // 4. ctx = att @ V  -> [b,s,h,hd] == [4096,1024]
    {
        dim3 grid(1, Sc / 128, Bc * Hc);
        ctx_kernel<<<grid, 256>>>(attp, qkvp, ctxp);
    }
    // 5. out = ctx @ Wo + bo
    {
        dim3 grid(Dc / 128, Mrows / 128);
        sgemm_bias_kernel<<<grid, 256>>>(ctxp, Wo, bo, outp, Mrows, Dc, Dc);
    }
}

// round 6
// speedup vs baseline: 2.5960x; 2.5960x over previous
#include <cuda_runtime.h>
#include <cuda_bf16.h>
#include <cstdint>
#include <cstddef>

// Problem constants
#define Bc   4
#define Sc   1024
#define Dc   1024
#define Hc   16
#define HDc  64
#define Mrows (Bc * Sc)          // 4096
#define NQKV  (3 * Dc)           // 3072

static const long OUT_ELEMS = (long)Bc * Sc * Dc;        // 4,194,304
static const long ATT_ELEMS = (long)Bc * Hc * Sc * Sc;   // 67,108,864

// Scratch (device globals — no allocations allowed)
__device__ float g_qkv[(size_t)Mrows * NQKV];            // 50 MB
__device__ float g_ctx[(size_t)Mrows * Dc];              // 16 MB
__device__ float g_att[(size_t)Bc * Hc * Sc * Sc];       // 268 MB (fallback if att not an output)

// ---------------------------------------------------------------------------
// tf32 helpers
// ---------------------------------------------------------------------------
__device__ __forceinline__ unsigned f2tf(float f) {
    unsigned u;
    asm("cvt.rna.tf32.f32 %0, %1;" : "=r"(u) : "f"(f));
    return u;
}

// D += A(16x8, row) * B(8x8, col) ; fp32 accum
__device__ __forceinline__ void mma8(float* d, const unsigned* a, const unsigned* b) {
    asm volatile(
        "mma.sync.aligned.m16n8k8.row.col.f32.tf32.tf32.f32 "
        "{%0,%1,%2,%3}, {%4,%5,%6,%7}, {%8,%9}, {%0,%1,%2,%3};\n"
        : "+f"(d[0]), "+f"(d[1]), "+f"(d[2]), "+f"(d[3])
        : "r"(a[0]), "r"(a[1]), "r"(a[2]), "r"(a[3]), "r"(b[0]), "r"(b[1]));
}

// ---------------------------------------------------------------------------
// tf32 SGEMM + bias: C[M,N] = A[M,K] @ B[K,N] + bias[N]
// 128x128 block tile, BK=16, double-buffered smem, 256 thr.
// Warp grid 2(M)x4(N): warp tile 64x32 -> 4 mtiles x 4 ntiles of m16n8k8.
// ---------------------------------------------------------------------------
__global__ __launch_bounds__(256) void sgemm_tf32_bias(
    const float* __restrict__ A, const float* __restrict__ B,
    const float* __restrict__ bias, float* __restrict__ C,
    int Md, int Nd, int Kd)
{
    __shared__ unsigned As[2][16][132];   // [stage][k][m]
    __shared__ unsigned Bs[2][16][132];   // [stage][k][n]

    const int t    = threadIdx.x;
    const int m0   = blockIdx.y * 128;
    const int n0   = blockIdx.x * 128;
    const int warp = t >> 5, lane = t & 31;
    const int wm   = (warp & 1) * 64;
    const int wn   = (warp >> 1) * 32;
    const int q    = lane >> 2, r = lane & 3;

    float acc[4][4][4];
#pragma unroll
    for (int mt = 0; mt < 4; ++mt)
#pragma unroll
        for (int nt = 0; nt < 4; ++nt)
#pragma unroll
            for (int i = 0; i < 4; ++i) acc[mt][nt][i] = 0.0f;

    // --- load tile 0 ---
#pragma unroll
    for (int i = 0; i < 2; ++i) {
        const int idx = t + i * 256;
        // A: 128(m) x 16(k): k4 = idx>>7, m = idx&127
        const int ak4 = idx >> 7, am = idx & 127;
        float4 av = *(const float4*)&A[(size_t)(m0 + am) * Kd + ak4 * 4];
        As[0][ak4 * 4 + 0][am] = f2tf(av.x);
        As[0][ak4 * 4 + 1][am] = f2tf(av.y);
        As[0][ak4 * 4 + 2][am] = f2tf(av.z);
        As[0][ak4 * 4 + 3][am] = f2tf(av.w);
        // B: 16(k) x 128(n): k = idx>>5, n4 = (idx&31)*4
        const int bk = idx >> 5, bn4 = (idx & 31) * 4;
        float4 bv = *(const float4*)&B[(size_t)bk * Nd + n0 + bn4];
        Bs[0][bk][bn4 + 0] = f2tf(bv.x);
        Bs[0][bk][bn4 + 1] = f2tf(bv.y);
        Bs[0][bk][bn4 + 2] = f2tf(bv.z);
        Bs[0][bk][bn4 + 3] = f2tf(bv.w);
    }
    __syncthreads();

    const int nK = Kd >> 4;
    for (int kt = 0; kt < nK; ++kt) {
        const int cur = kt & 1;
        float4 pa[2], pb[2];
        const bool pre = (kt + 1 < nK);
        if (pre) {
            const int kofs = (kt + 1) * 16;
#pragma unroll
            for (int i = 0; i < 2; ++i) {
                const int idx = t + i * 256;
                const int ak4 = idx >> 7, am = idx & 127;
                pa[i] = *(const float4*)&A[(size_t)(m0 + am) * Kd + kofs + ak4 * 4];
                const int bk = idx >> 5, bn4 = (idx & 31) * 4;
                pb[i] = *(const float4*)&B[(size_t)(kofs + bk) * Nd + n0 + bn4];
            }
        }

#pragma unroll
        for (int ks = 0; ks < 16; ks += 8) {
            unsigned af[4][4], bf[4][2];
#pragma unroll
            for (int mt = 0; mt < 4; ++mt) {
                const int mm = wm + mt * 16;
                af[mt][0] = As[cur][ks + r][mm + q];
                af[mt][1] = As[cur][ks + r][mm + q + 8];
                af[mt][2] = As[cur][ks + r + 4][mm + q];
                af[mt][3] = As[cur][ks + r + 4][mm + q + 8];
            }
#pragma unroll
            for (int nt = 0; nt < 4; ++nt) {
                const int nn = wn + nt * 8;
                bf[nt][0] = Bs[cur][ks + r][nn + q];
                bf[nt][1] = Bs[cur][ks + r + 4][nn + q];
            }
#pragma unroll
            for (int mt = 0; mt < 4; ++mt)
#pragma unroll
                for (int nt = 0; nt < 4; ++nt)
                    mma8(acc[mt][nt], af[mt], bf[nt]);
        }

        if (pre) {
            const int nxt = cur ^ 1;
#pragma unroll
            for (int i = 0; i < 2; ++i) {
                const int idx = t + i * 256;
                const int ak4 = idx >> 7, am = idx & 127;
                As[nxt][ak4 * 4 + 0][am] = f2tf(pa[i].x);
                As[nxt][ak4 * 4 + 1][am] = f2tf(pa[i].y);
                As[nxt][ak4 * 4 + 2][am] = f2tf(pa[i].z);
                As[nxt][ak4 * 4 + 3][am] = f2tf(pa[i].w);
                const int bk = idx >> 5, bn4 = (idx & 31) * 4;
                Bs[nxt][bk][bn4 + 0] = f2tf(pb[i].x);
                Bs[nxt][bk][bn4 + 1] = f2tf(pb[i].y);
                Bs[nxt][bk][bn4 + 2] = f2tf(pb[i].z);
                Bs[nxt][bk][bn4 + 3] = f2tf(pb[i].w);
            }
        }
        __syncthreads();
    }

    // Epilogue
#pragma unroll
    for (int mt = 0; mt < 4; ++mt) {
        const int row0 = m0 + wm + mt * 16 + q;
#pragma unroll
        for (int nt = 0; nt < 4; ++nt) {
            const int col = n0 + wn + nt * 8 + 2 * r;
            const float bx = bias[col], by = bias[col + 1];
            float2 v0 = make_float2(acc[mt][nt][0] + bx, acc[mt][nt][1] + by);
            float2 v1 = make_float2(acc[mt][nt][2] + bx, acc[mt][nt][3] + by);
            *(float2*)&C[(size_t)row0 * Nd + col] = v0;
            *(float2*)&C[(size_t)(row0 + 8) * Nd + col] = v1;
        }
    }
}

// ---------------------------------------------------------------------------
// scores[b,h,m,n] = (Q . K) * 0.125 + mask   via tf32 mma, K-dim=64
// Q/K strided in g_qkv (row stride 3072, head offset h*192, K at +64)
// ---------------------------------------------------------------------------
__global__ __launch_bounds__(256) void scores_tf32(
    const float* __restrict__ qkv, const float* __restrict__ mask,
    float* __restrict__ att)
{
    __shared__ unsigned Qs[2][16][132];   // [k][m]
    __shared__ unsigned Ks[2][16][132];   // [k][n]

    const int t    = threadIdx.x;
    const int bh   = blockIdx.z;
    const int b    = bh >> 4, h = bh & 15;
    const int m0   = blockIdx.y * 128;
    const int n0   = blockIdx.x * 128;
    const int warp = t >> 5, lane = t & 31;
    const int wm   = (warp & 1) * 64;
    const int wn   = (warp >> 1) * 32;
    const int q    = lane >> 2, r = lane & 3;

    const size_t qbase = (size_t)b * Sc * NQKV + (size_t)h * 192;

    float acc[4][4][4];
#pragma unroll
    for (int mt = 0; mt < 4; ++mt)
#pragma unroll
        for (int nt = 0; nt < 4; ++nt)
#pragma unroll
            for (int i = 0; i < 4; ++i) acc[mt][nt][i] = 0.0f;

    // tile 0
#pragma unroll
    for (int i = 0; i < 2; ++i) {
        const int idx = t + i * 256;
        const int k4 = idx >> 7, row = idx & 127;
        float4 qv = *(const float4*)&qkv[qbase + (size_t)(m0 + row) * NQKV + k4 * 4];
        float4 kv = *(const float4*)&qkv[qbase + (size_t)(n0 + row) * NQKV + 64 + k4 * 4];
        Qs[0][k4 * 4 + 0][row] = f2tf(qv.x);
        Qs[0][k4 * 4 + 1][row] = f2tf(qv.y);
        Qs[0][k4 * 4 + 2][row] = f2tf(qv.z);
        Qs[0][k4 * 4 + 3][row] = f2tf(qv.w);
        Ks[0][k4 * 4 + 0][row] = f2tf(kv.x);
        Ks[0][k4 * 4 + 1][row] = f2tf(kv.y);
        Ks[0][k4 * 4 + 2][row] = f2tf(kv.z);
        Ks[0][k4 * 4 + 3][row] = f2tf(kv.w);
    }
    __syncthreads();

    const int nK = 4;  // 64/16
#pragma unroll
    for (int kt = 0; kt < nK; ++kt) {
        const int cur = kt & 1;
        float4 pq[2], pk[2];
        const bool pre = (kt + 1 < nK);
        if (pre) {
            const int kofs = (kt + 1) * 16;
#pragma unroll
            for (int i = 0; i < 2; ++i) {
                const int idx = t + i * 256;
                const int k4 = idx >> 7, row = idx & 127;
                pq[i] = *(const float4*)&qkv[qbase + (size_t)(m0 + row) * NQKV + kofs + k4 * 4];
                pk[i] = *(const float4*)&qkv[qbase + (size_t)(n0 + row) * NQKV + 64 + kofs + k4 * 4];
            }
        }

#pragma unroll
        for (int ks = 0; ks < 16; ks += 8) {
            unsigned af[4][4], bf[4][2];
#pragma unroll
            for (int mt = 0; mt < 4; ++mt) {
                const int mm = wm + mt * 16;
                af[mt][0] = Qs[cur][ks + r][mm + q];
                af[mt][1] = Qs[cur][ks + r][mm + q + 8];
                af[mt][2] = Qs[cur][ks + r + 4][mm + q];
                af[mt][3] = Qs[cur][ks + r + 4][mm + q + 8];
            }
#pragma unroll
            for (int nt = 0; nt < 4; ++nt) {
                const int nn = wn + nt * 8;
                bf[nt][0] = Ks[cur][ks + r][nn + q];
                bf[nt][1] = Ks[cur][ks + r + 4][nn + q];
            }
#pragma unroll
            for (int mt = 0; mt < 4; ++mt)
#pragma unroll
                for (int nt = 0; nt < 4; ++nt)
                    mma8(acc[mt][nt], af[mt], bf[nt]);
        }

        if (pre) {
            const int nxt = cur ^ 1;
#pragma unroll
            for (int i = 0; i < 2; ++i) {
                const int idx = t + i * 256;
                const int k4 = idx >> 7, row = idx & 127;
                Qs[nxt][k4 * 4 + 0][row] = f2tf(pq[i].x);
                Qs[nxt][k4 * 4 + 1][row] = f2tf(pq[i].y);
                Qs[nxt][k4 * 4 + 2][row] = f2tf(pq[i].z);
                Qs[nxt][k4 * 4 + 3][row] = f2tf(pq[i].w);
                Ks[nxt][k4 * 4 + 0][row] = f2tf(pk[i].x);
                Ks[nxt][k4 * 4 + 1][row] = f2tf(pk[i].y);
                Ks[nxt][k4 * 4 + 2][row] = f2tf(pk[i].z);
                Ks[nxt][k4 * 4 + 3][row] = f2tf(pk[i].w);
            }
        }
        __syncthreads();
    }

    const float scale = 0.125f;
    const float* mbase = mask + (size_t)b * Sc * Sc;
    float* abase = att + (size_t)bh * Sc * Sc;

#pragma unroll
    for (int mt = 0; mt < 4; ++mt) {
        const int row0 = m0 + wm + mt * 16 + q;
#pragma unroll
        for (int nt = 0; nt < 4; ++nt) {
            const int col = n0 + wn + nt * 8 + 2 * r;
            float2 mv0 = *(const float2*)&mbase[(size_t)row0 * Sc + col];
            float2 mv1 = *(const float2*)&mbase[(size_t)(row0 + 8) * Sc + col];
            float2 v0 = make_float2(fmaf(acc[mt][nt][0], scale, mv0.x),
                                    fmaf(acc[mt][nt][1], scale, mv0.y));
            float2 v1 = make_float2(fmaf(acc[mt][nt][2], scale, mv1.x),
                                    fmaf(acc[mt][nt][3], scale, mv1.y));
            *(float2*)&abase[(size_t)row0 * Sc + col] = v0;
            *(float2*)&abase[(size_t)(row0 + 8) * Sc + col] = v1;
        }
    }
}

// ---------------------------------------------------------------------------
// In-place row softmax, warp-shuffle reductions. 1 block / row of 1024.
// ---------------------------------------------------------------------------
__global__ __launch_bounds__(256) void softmax_kernel(float* __restrict__ att)
{
    __shared__ float sred[8];
    float* row = att + (size_t)blockIdx.x * Sc;
    const int t = threadIdx.x;
    const int lane = t & 31, warp = t >> 5;

    float4 v = *(float4*)&row[t * 4];
    float mx = fmaxf(fmaxf(v.x, v.y), fmaxf(v.z, v.w));
#pragma unroll
    for (int o = 16; o > 0; o >>= 1)
        mx = fmaxf(mx, __shfl_xor_sync(0xffffffffu, mx, o));
    if (lane == 0) sred[warp] = mx;
    __syncthreads();
    mx = sred[0];
#pragma unroll
    for (int i = 1; i < 8; ++i) mx = fmaxf(mx, sred[i]);

    v.x = __expf(v.x - mx);
    v.y = __expf(v.y - mx);
    v.z = __expf(v.z - mx);
    v.w = __expf(v.w - mx);

    float sm = v.x + v.y + v.z + v.w;
#pragma unroll
    for (int o = 16; o > 0; o >>= 1)
        sm += __shfl_xor_sync(0xffffffffu, sm, o);
    __syncthreads();          // protect sred reuse
    if (lane == 0) sred[warp] = sm;
    __syncthreads();
    sm = sred[0];
#pragma unroll
    for (int i = 1; i < 8; ++i) sm += sred[i];

    const float inv = 1.0f / sm;
    v.x *= inv; v.y *= inv; v.z *= inv; v.w *= inv;
    *(float4*)&row[t * 4] = v;
}

// ---------------------------------------------------------------------------
// ctx = att @ V (per b,h: [1024,1024]@[1024,64]) via tf32 mma.
// Block 128(M)x64(N), BK=16 double-buffered. Warp grid 4(M)x2(N): 32x32/warp.
// ctx stored [b,s,h,hd] -> plain [4096,1024] for out-proj GEMM.
// ---------------------------------------------------------------------------
__global__ __launch_bounds__(256) void ctx_tf32(
    const float* __restrict__ att, const float* __restrict__ qkv,
    float* __restrict__ ctx)
{
    __shared__ unsigned As[2][16][132];   // att: [k][m]
    __shared__ unsigned Vs[2][16][68];    // V:   [k][n]

    const int t    = threadIdx.x;
    const int bh   = blockIdx.z;
    const int b    = bh >> 4, h = bh & 15;
    const int m0   = blockIdx.y * 128;
    const int warp = t >> 5, lane = t & 31;
    const int wm   = (warp & 3) * 32;
    const int wn   = (warp >> 2) * 32;
    const int q    = lane >> 2, r = lane & 3;

    const float* abase = att + (size_t)bh * Sc * Sc;
    const size_t vbase = (size_t)b * Sc * NQKV + (size_t)h * 192 + 128;

    float acc[2][4][4];
#pragma unroll
    for (int mt = 0; mt < 2; ++mt)
#pragma unroll
        for (int nt = 0; nt < 4; ++nt)
#pragma unroll
            for (int i = 0; i < 4; ++i) acc[mt][nt][i] = 0.0f;

    // tile 0
#pragma unroll
    for (int i = 0; i < 2; ++i) {
        const int idx = t + i * 256;
        const int k4 = idx >> 7, m = idx & 127;
        float4 av = *(const float4*)&abase[(size_t)(m0 + m) * Sc + k4 * 4];
        As[0][k4 * 4 + 0][m] = f2tf(av.x);
        As[0][k4 * 4 + 1][m] = f2tf(av.y);
        As[0][k4 * 4 + 2][m] = f2tf(av.z);
        As[0][k4 * 4 + 3][m] = f2tf(av.w);
    }
    {
        const int vk = t >> 4, vn4 = (t & 15) * 4;
        float4 vv = *(const float4*)&qkv[vbase + (size_t)vk * NQKV + vn4];
        Vs[0][vk][vn4 + 0] = f2tf(vv.x);
        Vs[0][vk][vn4 + 1] = f2tf(vv.y);
        Vs[0][vk][vn4 + 2] = f2tf(vv.z);
        Vs[0][vk][vn4 + 3] = f2tf(vv.w);
    }
    __syncthreads();

    const int nK = Sc >> 4;   // 64
    for (int kt = 0; kt < nK; ++kt) {
        const int cur = kt & 1;
        float4 pa[2], pv;
        const bool pre = (kt + 1 < nK);
        if (pre) {
            const int kofs = (kt + 1) * 16;
#pragma unroll
            for (int i = 0; i < 2; ++i) {
                const int idx = t + i * 256;
                const int k4 = idx >> 7, m = idx & 127;
                pa[i] = *(const float4*)&abase[(size_t)(m0 + m) * Sc + kofs + k4 * 4];
            }
            const int vk = t >> 4, vn4 = (t & 15) * 4;
            pv = *(const float4*)&qkv[vbase + (size_t)(kofs + vk) * NQKV + vn4];
        }

#pragma unroll
        for (int ks = 0; ks < 16; ks += 8) {
            unsigned af[2][4], bf[4][2];
#pragma unroll
            for (int mt = 0; mt < 2; ++mt) {
                const int mm = wm + mt * 16;
                af[mt][0] = As[cur][ks + r][mm + q];
                af[mt][1] = As[cur][ks + r][mm + q + 8];
                af[mt][2] = As[cur][ks + r + 4][mm + q];
                af[mt][3] = As[cur][ks + r + 4][mm + q + 8];
            }
#pragma unroll
            for (int nt = 0; nt < 4; ++nt) {
                const int nn = wn + nt * 8;
                bf[nt][0] = Vs[cur][ks + r][nn + q];
                bf[nt][1] = Vs[cur][ks + r + 4][nn + q];
            }
#pragma unroll
            for (int mt = 0; mt < 2; ++mt)
#pragma unroll
                for (int nt = 0; nt < 4; ++nt)
                    mma8(acc[mt][nt], af[mt], bf[nt]);
        }

        if (pre) {
            const int nxt = cur ^ 1;
#pragma unroll
            for (int i = 0; i < 2; ++i) {
                const int idx = t + i * 256;
                const int k4 = idx >> 7, m = idx & 127;
                As[nxt][k4 * 4 + 0][m] = f2tf(pa[i].x);
                As[nxt][k4 * 4 + 1][m] = f2tf(pa[i].y);
                As[nxt][k4 * 4 + 2][m] = f2tf(pa[i].z);
                As[nxt][k4 * 4 + 3][m] = f2tf(pa[i].w);
            }
            const int vk = t >> 4, vn4 = (t & 15) * 4;
            Vs[nxt][vk][vn4 + 0] = f2tf(pv.x);
            Vs[nxt][vk][vn4 + 1] = f2tf(pv.y);
            Vs[nxt][vk][vn4 + 2] = f2tf(pv.z);
            Vs[nxt][vk][vn4 + 3] = f2tf(pv.w);
        }
        __syncthreads();
    }

    // Epilogue: ctx[b, m, h, :]
#pragma unroll
    for (int mt = 0; mt < 2; ++mt) {
        const int row0 = m0 + wm + mt * 16 + q;
#pragma unroll
        for (int nt = 0; nt < 4; ++nt) {
            const int col = wn + nt * 8 + 2 * r;
            float2 v0 = make_float2(acc[mt][nt][0], acc[mt][nt][1]);
            float2 v1 = make_float2(acc[mt][nt][2], acc[mt][nt][3]);
            *(float2*)&ctx[(size_t)(b * Sc + row0) * Dc + h * HDc + col] = v0;
            *(float2*)&ctx[(size_t)(b * Sc + row0 + 8) * Dc + h * HDc + col] = v1;
        }
    }
}

// ---------------------------------------------------------------------------
// Launch
// ---------------------------------------------------------------------------
extern "C" void kernel_launch(void* const* d_in, const int* in_sizes, int n_in,
                              void* d_out, int out_size)
{
    const float* x    = (const float*)d_in[0];
    const float* mask = (const float*)d_in[1];
    const float* Wqkv = (const float*)d_in[2];
    const float* bqkv = (const float*)d_in[3];
    const float* Wo   = (const float*)d_in[4];
    const float* bo   = (const float*)d_in[5];

    float *qkvp, *ctxp, *attScr;
    cudaGetSymbolAddress((void**)&qkvp,  g_qkv);
    cudaGetSymbolAddress((void**)&ctxp,  g_ctx);
    cudaGetSymbolAddress((void**)&attScr, g_att);

    float* outp = (float*)d_out;
    float* attp;
    if ((long)out_size >= OUT_ELEMS + ATT_ELEMS) {
        attp = (float*)d_out + OUT_ELEMS;          // tuple flattened: out, then att
    } else if ((long)out_size == ATT_ELEMS) {
        attp = (float*)d_out;                      // att-only output
        outp = qkvp;                               // sink (qkv dead by then)
    } else {
        attp = attScr;                             // out-only output
    }

    // 1. qkv = x @ Wqkv + bqkv        [4096,3072]
    {
        dim3 grid(NQKV / 128, Mrows / 128);
        sgemm_tf32_bias<<<grid, 256>>>(x, Wqkv, bqkv, qkvp, Mrows, NQKV, Dc);
    }
    // 2. scores (*scale + mask) -> att buffer
    {
        dim3 grid(Sc / 128, Sc / 128, Bc * Hc);
        scores_tf32<<<grid, 256>>>(qkvp, mask, attp);
    }
    // 3. softmax rows in place
    softmax_kernel<<<Bc * Hc * Sc, 256>>>(attp);
    // 4. ctx = att @ V  -> [b,s,h,hd] == [4096,1024]
    {
        dim3 grid(1, Sc / 128, Bc * Hc);
        ctx_tf32<<<grid, 256>>>(attp, qkvp, ctxp);
    }
    // 5. out = ctx @ Wo + bo
    {
        dim3 grid(Dc / 128, Mrows / 128);
        sgemm_tf32_bias<<<grid, 256>>>(ctxp, Wo, bo, outp, Mrows, Dc, Dc);
    }
}